// round 5
// baseline (speedup 1.0000x reference)
#include <cuda_runtime.h>

#define NN 100000
#define NE 1600000

// ---- scratch (device globals: no allocation allowed) ----
__device__ float g_deg[NN];            // weighted in-degree, then dinv in place
__device__ int   g_cnt[NN];            // in-degree count (histogram)
__device__ int   g_cur[NN];            // fill cursors
__device__ int   g_off[NN + 1];        // CSR row offsets (by dst)
__device__ int   g_csrc[NE];           // CSR: source node per slot
__device__ float g_cnorm[NE];          // CSR: norm per slot
__device__ float g_h1[NN * 48];
__device__ float g_acc1[NN * 48];
__device__ float g_h2[NN * 40];

__device__ __forceinline__ float neg_inf() { return __int_as_float(0xff800000); }

// Zero per-call accumulators (graph-capture-safe: kernel, not memset node).
__global__ void __launch_bounds__(256) zero_init() {
    int i = blockIdx.x * blockDim.x + threadIdx.x;
    if (i < NN) {
        g_deg[i] = 0.f;
        g_cnt[i] = 0;
        g_cur[i] = 0;
    }
}

// Pass 1: weighted in-degree + count histogram. edge_index is int32 [2, NE].
__global__ void __launch_bounds__(256)
prep_edges(const int* __restrict__ ei, const float* __restrict__ ew) {
    int e = blockIdx.x * blockDim.x + threadIdx.x;
    if (e >= NE) return;
    int d = ei[NE + e];
    atomicAdd(&g_deg[d], ew[e]);
    atomicAdd(&g_cnt[d], 1);
}

__global__ void __launch_bounds__(256) finish_dinv() {
    int i = blockIdx.x * blockDim.x + threadIdx.x;
    if (i >= NN) return;
    float d = g_deg[i];
    g_deg[i] = (d > 0.f) ? rsqrtf(d) : 0.f;
}

// Single-block exclusive scan of g_cnt -> g_off (1024 threads, chunked).
__global__ void __launch_bounds__(1024) scan_offsets() {
    const int T = 1024;
    const int CHUNK = (NN + T - 1) / T;          // 98
    __shared__ int sums[T];
    int tid = threadIdx.x;
    int base = tid * CHUNK;

    int s = 0;
    for (int i = 0; i < CHUNK; i++) {
        int idx = base + i;
        if (idx < NN) s += g_cnt[idx];
    }
    sums[tid] = s;
    __syncthreads();

    for (int off = 1; off < T; off <<= 1) {
        int v = (tid >= off) ? sums[tid - off] : 0;
        __syncthreads();
        sums[tid] += v;
        __syncthreads();
    }

    int running = sums[tid] - s;                  // exclusive prefix of this chunk
    for (int i = 0; i < CHUNK; i++) {
        int idx = base + i;
        if (idx < NN) {
            g_off[idx] = running;
            running += g_cnt[idx];
        }
    }
    if (tid == T - 1) g_off[NN] = sums[T - 1];
}

// Pass 2: compute norm, scatter edges into CSR slots (grouped by dst).
__global__ void __launch_bounds__(256)
fill_csr(const int* __restrict__ ei, const float* __restrict__ ew) {
    int e = blockIdx.x * blockDim.x + threadIdx.x;
    if (e >= NE) return;
    int s = ei[e];
    int d = ei[NE + e];
    float nm = g_deg[s] * ew[e] * g_deg[d];
    int pos = g_off[d] + atomicAdd(&g_cur[d], 1);
    g_csrc[pos]  = s;
    g_cnorm[pos] = nm;
}

// Dual GEMM: h = act(x) @ W ; acc = act(x) @ V + b.  W,V row-major [FIN, FOUT].
template <int FIN, int FOUT, bool RELU>
__global__ void __launch_bounds__(FOUT * 4)
gemm_dual(const float* __restrict__ x, const float* __restrict__ W,
          const float* __restrict__ V, const float* __restrict__ b,
          float* __restrict__ h, float* __restrict__ acc) {
    __shared__ float2 WV[FIN * FOUT];
    __shared__ float  xs[16][FIN + 1];

    const int tid = threadIdx.y * FOUT + threadIdx.x;
    const int nth = FOUT * 4;

    for (int i = tid; i < FIN * FOUT; i += nth)
        WV[i] = make_float2(W[i], V[i]);

    const int row0 = blockIdx.x * 16;
    for (int i = tid; i < 16 * FIN; i += nth) {
        int r = i / FIN, c = i - r * FIN;
        float v = x[(size_t)(row0 + r) * FIN + c];
        if (RELU) v = fmaxf(v, 0.f);
        xs[r][c] = v;
    }
    __syncthreads();

    const int f = threadIdx.x;
    float aW[4] = {0.f, 0.f, 0.f, 0.f};
    float aV[4] = {0.f, 0.f, 0.f, 0.f};

#pragma unroll 8
    for (int k = 0; k < FIN; k++) {
        float2 wv = WV[k * FOUT + f];
#pragma unroll
        for (int j = 0; j < 4; j++) {
            float xv = xs[threadIdx.y + j * 4][k];
            aW[j] = fmaf(xv, wv.x, aW[j]);
            aV[j] = fmaf(xv, wv.y, aV[j]);
        }
    }

    const float bf = b[f];
#pragma unroll
    for (int j = 0; j < 4; j++) {
        int gr = row0 + threadIdx.y + j * 4;
        h[(size_t)gr * FOUT + f]   = aW[j];
        acc[(size_t)gr * FOUT + f] = aV[j] + bf;
    }
}

// CSR aggregation: one warp per node; register accumulators, no atomics.
// acc preloaded with x@V + b; adds sum_e norm_e * h[src_e].
template <int FOUT>
__global__ void __launch_bounds__(256)
agg_csr(const float* __restrict__ h, float* __restrict__ acc) {
    int gw = (blockIdx.x * blockDim.x + threadIdx.x) >> 5;
    if (gw >= NN) return;
    int lane = threadIdx.x & 31;

    int e0 = g_off[gw];
    int e1 = g_off[gw + 1];

    float a0 = acc[(size_t)gw * FOUT + lane];
    float a1 = (lane < FOUT - 32) ? acc[(size_t)gw * FOUT + 32 + lane] : 0.f;

    for (int e = e0; e < e1; e++) {
        int   s  = g_csrc[e];
        float nm = g_cnorm[e];
        const float* hr = h + (size_t)s * FOUT;
        a0 = fmaf(hr[lane], nm, a0);
        if (lane < FOUT - 32) a1 = fmaf(hr[32 + lane], nm, a1);
    }

    acc[(size_t)gw * FOUT + lane] = a0;
    if (lane < FOUT - 32) acc[(size_t)gw * FOUT + 32 + lane] = a1;
}

// Final: out_row = log_softmax(relu(acc_row)), one warp per node (40 classes).
__global__ void __launch_bounds__(256) logsoftmax_relu(float* __restrict__ out) {
    int gw = (blockIdx.x * blockDim.x + threadIdx.x) >> 5;
    if (gw >= NN) return;
    int lane = threadIdx.x & 31;
    float* row = out + (size_t)gw * 40;

    float v0 = fmaxf(row[lane], 0.f);
    float v1 = (lane < 8) ? fmaxf(row[32 + lane], 0.f) : neg_inf();

    float m = fmaxf(v0, v1);
#pragma unroll
    for (int o = 16; o; o >>= 1) m = fmaxf(m, __shfl_xor_sync(0xffffffffu, m, o));

    float sv = __expf(v0 - m) + ((lane < 8) ? __expf(v1 - m) : 0.f);
#pragma unroll
    for (int o = 16; o; o >>= 1) sv += __shfl_xor_sync(0xffffffffu, sv, o);

    float lse = m + __logf(sv);
    row[lane] = v0 - lse;
    if (lane < 8) row[32 + lane] = v1 - lse;
}

extern "C" void kernel_launch(void* const* d_in, const int* in_sizes, int n_in,
                              void* d_out, int out_size) {
    const float* x  = (const float*)d_in[0];
    const int*   ei = (const int*)d_in[1];      // int32 [2, NE] (JAX x64 disabled)
    const float* ew = (const float*)d_in[2];
    const float* W1 = (const float*)d_in[3];
    const float* V1 = (const float*)d_in[4];
    const float* b1 = (const float*)d_in[5];
    const float* W2 = (const float*)d_in[6];
    const float* V2 = (const float*)d_in[7];
    const float* b2 = (const float*)d_in[8];
    float* out = (float*)d_out;

    void *h1p, *acc1p, *h2p;
    cudaGetSymbolAddress(&h1p,   g_h1);
    cudaGetSymbolAddress(&acc1p, g_acc1);
    cudaGetSymbolAddress(&h2p,   g_h2);

    zero_init   <<<(NN + 255) / 256, 256>>>();
    prep_edges  <<<(NE + 255) / 256, 256>>>(ei, ew);
    finish_dinv <<<(NN + 255) / 256, 256>>>();
    scan_offsets<<<1, 1024>>>();
    fill_csr    <<<(NE + 255) / 256, 256>>>(ei, ew);

    gemm_dual<64, 48, false><<<NN / 16, dim3(48, 4)>>>(
        x, W1, V1, b1, (float*)h1p, (float*)acc1p);

    agg_csr<48><<<(NN * 32 + 255) / 256, 256>>>((const float*)h1p, (float*)acc1p);

    gemm_dual<48, 40, true><<<NN / 16, dim3(40, 4)>>>(
        (const float*)acc1p, W2, V2, b2, (float*)h2p, out);

    agg_csr<40><<<(NN * 32 + 255) / 256, 256>>>((const float*)h2p, out);

    logsoftmax_relu<<<(NN * 32 + 255) / 256, 256>>>(out);
}

// round 6
// speedup vs baseline: 1.2531x; 1.2531x over previous
#include <cuda_runtime.h>

#define NN 100000
#define NE 1600000

#define SCAN_B 1024
#define NBLK ((NN + SCAN_B - 1) / SCAN_B)   // 98

// ---- scratch (device globals: no allocation allowed) ----
__device__ float g_deg[NN];            // weighted in-degree, then dinv in place
__device__ int   g_cnt[NN];            // in-degree count (histogram)
__device__ int   g_cur[NN];            // fill cursors
__device__ int   g_off[NN + 1];        // CSR row offsets (by dst)
__device__ int   g_bsum[NBLK];         // per-block sums
__device__ int   g_bpre[NBLK];         // per-block exclusive prefixes
__device__ int   g_csrc[NE];           // CSR: source node per slot
__device__ float g_cnorm[NE];          // CSR: norm per slot
__device__ float g_h1[NN * 48];
__device__ float g_acc1[NN * 48];
__device__ float g_h2[NN * 40];

__device__ __forceinline__ float neg_inf() { return __int_as_float(0xff800000); }

// Zero per-call accumulators (graph-capture-safe: kernel, not memset node).
__global__ void __launch_bounds__(256) zero_init() {
    int i = blockIdx.x * blockDim.x + threadIdx.x;
    if (i < NN) {
        g_deg[i] = 0.f;
        g_cnt[i] = 0;
        g_cur[i] = 0;
    }
}

// Pass 1: weighted in-degree + count histogram. edge_index is int32 [2, NE].
__global__ void __launch_bounds__(256)
prep_edges(const int* __restrict__ ei, const float* __restrict__ ew) {
    int e = blockIdx.x * blockDim.x + threadIdx.x;
    if (e >= NE) return;
    int d = ei[NE + e];
    atomicAdd(&g_deg[d], ew[e]);
    atomicAdd(&g_cnt[d], 1);
}

__global__ void __launch_bounds__(256) finish_dinv() {
    int i = blockIdx.x * blockDim.x + threadIdx.x;
    if (i >= NN) return;
    float d = g_deg[i];
    g_deg[i] = (d > 0.f) ? rsqrtf(d) : 0.f;
}

// ---- 3-phase multi-block exclusive scan of g_cnt -> g_off ----
__global__ void __launch_bounds__(SCAN_B) scan_phase1() {
    __shared__ int sums[SCAN_B];
    int tid = threadIdx.x;
    int i = blockIdx.x * SCAN_B + tid;
    int v = (i < NN) ? g_cnt[i] : 0;
    sums[tid] = v;
    __syncthreads();
#pragma unroll
    for (int off = 1; off < SCAN_B; off <<= 1) {
        int t = (tid >= off) ? sums[tid - off] : 0;
        __syncthreads();
        sums[tid] += t;
        __syncthreads();
    }
    if (i < NN) g_off[i] = sums[tid] - v;          // block-local exclusive
    if (tid == SCAN_B - 1) g_bsum[blockIdx.x] = sums[tid];
}

__global__ void __launch_bounds__(128) scan_phase2() {
    __shared__ int sums[128];
    int tid = threadIdx.x;
    int v = (tid < NBLK) ? g_bsum[tid] : 0;
    sums[tid] = v;
    __syncthreads();
#pragma unroll
    for (int off = 1; off < 128; off <<= 1) {
        int t = (tid >= off) ? sums[tid - off] : 0;
        __syncthreads();
        sums[tid] += t;
        __syncthreads();
    }
    if (tid < NBLK) g_bpre[tid] = sums[tid] - v;
}

__global__ void __launch_bounds__(256) scan_phase3() {
    int i = blockIdx.x * blockDim.x + threadIdx.x;
    if (i < NN) g_off[i] += g_bpre[i >> 10];
    if (i == 0) g_off[NN] = NE;
}

// Pass 2: compute norm, scatter edges into CSR slots (grouped by dst).
__global__ void __launch_bounds__(256)
fill_csr(const int* __restrict__ ei, const float* __restrict__ ew) {
    int e = blockIdx.x * blockDim.x + threadIdx.x;
    if (e >= NE) return;
    int s = ei[e];
    int d = ei[NE + e];
    float nm = g_deg[s] * ew[e] * g_deg[d];
    int pos = g_off[d] + atomicAdd(&g_cur[d], 1);
    g_csrc[pos]  = s;
    g_cnorm[pos] = nm;
}

// Dual GEMM: h = act(x) @ W ; acc = act(x) @ V + b.  W,V row-major [FIN, FOUT].
template <int FIN, int FOUT, bool RELU>
__global__ void __launch_bounds__(FOUT * 4)
gemm_dual(const float* __restrict__ x, const float* __restrict__ W,
          const float* __restrict__ V, const float* __restrict__ b,
          float* __restrict__ h, float* __restrict__ acc) {
    __shared__ float2 WV[FIN * FOUT];
    __shared__ float  xs[16][FIN + 1];

    const int tid = threadIdx.y * FOUT + threadIdx.x;
    const int nth = FOUT * 4;

    for (int i = tid; i < FIN * FOUT; i += nth)
        WV[i] = make_float2(W[i], V[i]);

    const int row0 = blockIdx.x * 16;
    for (int i = tid; i < 16 * FIN; i += nth) {
        int r = i / FIN, c = i - r * FIN;
        float v = x[(size_t)(row0 + r) * FIN + c];
        if (RELU) v = fmaxf(v, 0.f);
        xs[r][c] = v;
    }
    __syncthreads();

    const int f = threadIdx.x;
    float aW[4] = {0.f, 0.f, 0.f, 0.f};
    float aV[4] = {0.f, 0.f, 0.f, 0.f};

#pragma unroll 8
    for (int k = 0; k < FIN; k++) {
        float2 wv = WV[k * FOUT + f];
#pragma unroll
        for (int j = 0; j < 4; j++) {
            float xv = xs[threadIdx.y + j * 4][k];
            aW[j] = fmaf(xv, wv.x, aW[j]);
            aV[j] = fmaf(xv, wv.y, aV[j]);
        }
    }

    const float bf = b[f];
#pragma unroll
    for (int j = 0; j < 4; j++) {
        int gr = row0 + threadIdx.y + j * 4;
        h[(size_t)gr * FOUT + f]   = aW[j];
        acc[(size_t)gr * FOUT + f] = aV[j] + bf;
    }
}

// CSR aggregation: one warp per node; register accumulators, no atomics.
// 2-way unrolled to raise MLP (edge record + row gather overlap).
template <int FOUT>
__global__ void __launch_bounds__(256)
agg_csr(const float* __restrict__ h, float* __restrict__ acc) {
    int gw = (blockIdx.x * blockDim.x + threadIdx.x) >> 5;
    if (gw >= NN) return;
    int lane = threadIdx.x & 31;

    int e0 = g_off[gw];
    int e1 = g_off[gw + 1];

    float a0 = acc[(size_t)gw * FOUT + lane];
    float a1 = (lane < FOUT - 32) ? acc[(size_t)gw * FOUT + 32 + lane] : 0.f;

    int e = e0;
    for (; e + 2 <= e1; e += 2) {
        int   s0  = g_csrc[e];
        int   s1  = g_csrc[e + 1];
        float nm0 = g_cnorm[e];
        float nm1 = g_cnorm[e + 1];
        const float* hr0 = h + (size_t)s0 * FOUT;
        const float* hr1 = h + (size_t)s1 * FOUT;
        float v00 = hr0[lane];
        float v10 = hr1[lane];
        float v01 = 0.f, v11 = 0.f;
        if (lane < FOUT - 32) { v01 = hr0[32 + lane]; v11 = hr1[32 + lane]; }
        a0 = fmaf(v00, nm0, a0);
        a0 = fmaf(v10, nm1, a0);
        a1 = fmaf(v01, nm0, a1);
        a1 = fmaf(v11, nm1, a1);
    }
    if (e < e1) {
        int   s  = g_csrc[e];
        float nm = g_cnorm[e];
        const float* hr = h + (size_t)s * FOUT;
        a0 = fmaf(hr[lane], nm, a0);
        if (lane < FOUT - 32) a1 = fmaf(hr[32 + lane], nm, a1);
    }

    acc[(size_t)gw * FOUT + lane] = a0;
    if (lane < FOUT - 32) acc[(size_t)gw * FOUT + 32 + lane] = a1;
}

// Final: out_row = log_softmax(relu(acc_row)), one warp per node (40 classes).
__global__ void __launch_bounds__(256) logsoftmax_relu(float* __restrict__ out) {
    int gw = (blockIdx.x * blockDim.x + threadIdx.x) >> 5;
    if (gw >= NN) return;
    int lane = threadIdx.x & 31;
    float* row = out + (size_t)gw * 40;

    float v0 = fmaxf(row[lane], 0.f);
    float v1 = (lane < 8) ? fmaxf(row[32 + lane], 0.f) : neg_inf();

    float m = fmaxf(v0, v1);
#pragma unroll
    for (int o = 16; o; o >>= 1) m = fmaxf(m, __shfl_xor_sync(0xffffffffu, m, o));

    float sv = __expf(v0 - m) + ((lane < 8) ? __expf(v1 - m) : 0.f);
#pragma unroll
    for (int o = 16; o; o >>= 1) sv += __shfl_xor_sync(0xffffffffu, sv, o);

    float lse = m + __logf(sv);
    row[lane] = v0 - lse;
    if (lane < 8) row[32 + lane] = v1 - lse;
}

extern "C" void kernel_launch(void* const* d_in, const int* in_sizes, int n_in,
                              void* d_out, int out_size) {
    const float* x  = (const float*)d_in[0];
    const int*   ei = (const int*)d_in[1];      // int32 [2, NE]
    const float* ew = (const float*)d_in[2];
    const float* W1 = (const float*)d_in[3];
    const float* V1 = (const float*)d_in[4];
    const float* b1 = (const float*)d_in[5];
    const float* W2 = (const float*)d_in[6];
    const float* V2 = (const float*)d_in[7];
    const float* b2 = (const float*)d_in[8];
    float* out = (float*)d_out;

    void *h1p, *acc1p, *h2p;
    cudaGetSymbolAddress(&h1p,   g_h1);
    cudaGetSymbolAddress(&acc1p, g_acc1);
    cudaGetSymbolAddress(&h2p,   g_h2);

    zero_init   <<<(NN + 255) / 256, 256>>>();
    prep_edges  <<<(NE + 255) / 256, 256>>>(ei, ew);
    finish_dinv <<<(NN + 255) / 256, 256>>>();
    scan_phase1 <<<NBLK, SCAN_B>>>();
    scan_phase2 <<<1, 128>>>();
    scan_phase3 <<<(NN + 255) / 256, 256>>>();
    fill_csr    <<<(NE + 255) / 256, 256>>>(ei, ew);

    gemm_dual<64, 48, false><<<NN / 16, dim3(48, 4)>>>(
        x, W1, V1, b1, (float*)h1p, (float*)acc1p);

    agg_csr<48><<<(NN * 32 + 255) / 256, 256>>>((const float*)h1p, (float*)acc1p);

    gemm_dual<48, 40, true><<<NN / 16, dim3(40, 4)>>>(
        (const float*)acc1p, W2, V2, b2, (float*)h2p, out);

    agg_csr<40><<<(NN * 32 + 255) / 256, 256>>>((const float*)h2p, out);

    logsoftmax_relu<<<(NN * 32 + 255) / 256, 256>>>(out);
}

// round 7
// speedup vs baseline: 1.5538x; 1.2400x over previous
#include <cuda_runtime.h>

#define NN 100000
#define NE 1600000

#define SCAN_B 1024
#define NBLK ((NN + SCAN_B - 1) / SCAN_B)   // 98

// ---- scratch (device globals: no allocation allowed) ----
__device__ float g_deg[NN];            // weighted in-degree, then dinv in place
__device__ int   g_cnt[NN];            // in-degree count (histogram)
__device__ int   g_cur[NN];            // fill cursors
__device__ int   g_off[NN + 1];        // CSR row offsets (by dst)
__device__ int   g_bsum[NBLK];         // per-block sums
__device__ int   g_bpre[NBLK];         // per-block exclusive prefixes
__device__ int2  g_edge[NE];           // CSR slot: {src, norm bits}
__device__ float g_h1[NN * 48];
__device__ float g_acc1[NN * 48];
__device__ float g_h2[NN * 40];
__device__ float g_acc2[NN * 40];

__device__ __forceinline__ float neg_inf() { return __int_as_float(0xff800000); }

__global__ void __launch_bounds__(256) zero_init() {
    int i = blockIdx.x * blockDim.x + threadIdx.x;
    if (i < NN) {
        g_deg[i] = 0.f;
        g_cnt[i] = 0;
        g_cur[i] = 0;
    }
}

// Pass 1: weighted in-degree + count histogram. edge_index is int32 [2, NE].
__global__ void __launch_bounds__(256)
prep_edges(const int* __restrict__ ei, const float* __restrict__ ew) {
    int e = blockIdx.x * blockDim.x + threadIdx.x;
    if (e >= NE) return;
    int d = ei[NE + e];
    atomicAdd(&g_deg[d], ew[e]);
    atomicAdd(&g_cnt[d], 1);
}

__global__ void __launch_bounds__(256) finish_dinv() {
    int i = blockIdx.x * blockDim.x + threadIdx.x;
    if (i >= NN) return;
    float d = g_deg[i];
    g_deg[i] = (d > 0.f) ? rsqrtf(d) : 0.f;
}

// ---- 3-phase multi-block exclusive scan of g_cnt -> g_off ----
__global__ void __launch_bounds__(SCAN_B) scan_phase1() {
    __shared__ int sums[SCAN_B];
    int tid = threadIdx.x;
    int i = blockIdx.x * SCAN_B + tid;
    int v = (i < NN) ? g_cnt[i] : 0;
    sums[tid] = v;
    __syncthreads();
#pragma unroll
    for (int off = 1; off < SCAN_B; off <<= 1) {
        int t = (tid >= off) ? sums[tid - off] : 0;
        __syncthreads();
        sums[tid] += t;
        __syncthreads();
    }
    if (i < NN) g_off[i] = sums[tid] - v;
    if (tid == SCAN_B - 1) g_bsum[blockIdx.x] = sums[tid];
}

__global__ void __launch_bounds__(128) scan_phase2() {
    __shared__ int sums[128];
    int tid = threadIdx.x;
    int v = (tid < NBLK) ? g_bsum[tid] : 0;
    sums[tid] = v;
    __syncthreads();
#pragma unroll
    for (int off = 1; off < 128; off <<= 1) {
        int t = (tid >= off) ? sums[tid - off] : 0;
        __syncthreads();
        sums[tid] += t;
        __syncthreads();
    }
    if (tid < NBLK) g_bpre[tid] = sums[tid] - v;
}

__global__ void __launch_bounds__(256) scan_phase3() {
    int i = blockIdx.x * blockDim.x + threadIdx.x;
    if (i < NN) g_off[i] += g_bpre[i >> 10];
    if (i == 0) g_off[NN] = NE;
}

// Pass 2: compute norm, scatter {src, norm} records into CSR slots.
__global__ void __launch_bounds__(256)
fill_csr(const int* __restrict__ ei, const float* __restrict__ ew) {
    int e = blockIdx.x * blockDim.x + threadIdx.x;
    if (e >= NE) return;
    int s = ei[e];
    int d = ei[NE + e];
    float nm = g_deg[s] * ew[e] * g_deg[d];
    int pos = g_off[d] + atomicAdd(&g_cur[d], 1);
    g_edge[pos] = make_int2(s, __float_as_int(nm));
}

// Dual GEMM: h = act(x) @ W ; acc = act(x) @ V + b.  W,V row-major [FIN, FOUT].
// 64 node-rows per block; float4 smem reads; each thread -> 16 rows of feature f.
template <int FIN, int FOUT, bool RELU>
__global__ void __launch_bounds__(FOUT * 4)
gemm_dual(const float* __restrict__ x, const float* __restrict__ W,
          const float* __restrict__ V, const float* __restrict__ b,
          float* __restrict__ h, float* __restrict__ acc) {
    constexpr int ROWS = 64;
    constexpr int STR  = FIN + 4;          // float4-aligned row stride
    constexpr int JR   = ROWS / 4;         // 16 rows per thread
    __shared__ float2 WV[FIN * FOUT];
    __shared__ float  xs[ROWS * STR];

    const int tid = threadIdx.y * FOUT + threadIdx.x;
    const int nth = FOUT * 4;

    for (int i = tid; i < FIN * FOUT; i += nth)
        WV[i] = make_float2(W[i], V[i]);

    const int row0 = blockIdx.x * ROWS;
    for (int i = tid; i < ROWS * FIN; i += nth) {
        int r = i / FIN, c = i - r * FIN;
        int gr = row0 + r;
        float v = (gr < NN) ? x[(size_t)gr * FIN + c] : 0.f;
        if (RELU) v = fmaxf(v, 0.f);
        xs[r * STR + c] = v;
    }
    __syncthreads();

    const int f = threadIdx.x;
    float aW[JR], aV[JR];
#pragma unroll
    for (int j = 0; j < JR; j++) { aW[j] = 0.f; aV[j] = 0.f; }

    for (int k = 0; k < FIN; k += 4) {
        float2 wv0 = WV[(k + 0) * FOUT + f];
        float2 wv1 = WV[(k + 1) * FOUT + f];
        float2 wv2 = WV[(k + 2) * FOUT + f];
        float2 wv3 = WV[(k + 3) * FOUT + f];
#pragma unroll
        for (int j = 0; j < JR; j++) {
            const float4 xv = *reinterpret_cast<const float4*>(
                &xs[(threadIdx.y + j * 4) * STR + k]);
            aW[j] = fmaf(xv.x, wv0.x, aW[j]); aV[j] = fmaf(xv.x, wv0.y, aV[j]);
            aW[j] = fmaf(xv.y, wv1.x, aW[j]); aV[j] = fmaf(xv.y, wv1.y, aV[j]);
            aW[j] = fmaf(xv.z, wv2.x, aW[j]); aV[j] = fmaf(xv.z, wv2.y, aV[j]);
            aW[j] = fmaf(xv.w, wv3.x, aW[j]); aV[j] = fmaf(xv.w, wv3.y, aV[j]);
        }
    }

    const float bf = b[f];
#pragma unroll
    for (int j = 0; j < JR; j++) {
        int gr = row0 + threadIdx.y + j * 4;
        if (gr < NN) {
            h[(size_t)gr * FOUT + f]   = aW[j];
            acc[(size_t)gr * FOUT + f] = aV[j] + bf;
        }
    }
}

// CSR aggregation: one warp per node. Lanes coalesced-load 32 edge records,
// shuffle-broadcast, 4 independent row gathers in flight. Optional fused
// relu+log_softmax epilogue (layer 2).
template <int FOUT, bool LSM>
__global__ void __launch_bounds__(256)
agg_csr(const float* __restrict__ h, const float* __restrict__ accin,
        float* __restrict__ out) {
    int gw = (blockIdx.x * blockDim.x + threadIdx.x) >> 5;
    if (gw >= NN) return;
    int lane = threadIdx.x & 31;

    int e0 = g_off[gw];
    int e1 = g_off[gw + 1];

    float a0 = accin[(size_t)gw * FOUT + lane];
    float a1 = (lane < FOUT - 32) ? accin[(size_t)gw * FOUT + 32 + lane] : 0.f;

    for (int base = e0; base < e1; base += 32) {
        int idx = base + lane;
        int2 rec = (idx < e1) ? g_edge[idx] : make_int2(0, 0);
        int cnt = min(32, e1 - base);
        int j = 0;
        for (; j + 4 <= cnt; j += 4) {
            int s0 = __shfl_sync(0xffffffffu, rec.x, j);
            int s1 = __shfl_sync(0xffffffffu, rec.x, j + 1);
            int s2 = __shfl_sync(0xffffffffu, rec.x, j + 2);
            int s3 = __shfl_sync(0xffffffffu, rec.x, j + 3);
            float n0 = __int_as_float(__shfl_sync(0xffffffffu, rec.y, j));
            float n1 = __int_as_float(__shfl_sync(0xffffffffu, rec.y, j + 1));
            float n2 = __int_as_float(__shfl_sync(0xffffffffu, rec.y, j + 2));
            float n3 = __int_as_float(__shfl_sync(0xffffffffu, rec.y, j + 3));
            const float* r0 = h + (size_t)s0 * FOUT;
            const float* r1 = h + (size_t)s1 * FOUT;
            const float* r2 = h + (size_t)s2 * FOUT;
            const float* r3 = h + (size_t)s3 * FOUT;
            float x0 = r0[lane], x1 = r1[lane], x2 = r2[lane], x3 = r3[lane];
            float y0 = 0.f, y1 = 0.f, y2 = 0.f, y3 = 0.f;
            if (lane < FOUT - 32) {
                y0 = r0[32 + lane]; y1 = r1[32 + lane];
                y2 = r2[32 + lane]; y3 = r3[32 + lane];
            }
            a0 = fmaf(x0, n0, a0); a0 = fmaf(x1, n1, a0);
            a0 = fmaf(x2, n2, a0); a0 = fmaf(x3, n3, a0);
            a1 = fmaf(y0, n0, a1); a1 = fmaf(y1, n1, a1);
            a1 = fmaf(y2, n2, a1); a1 = fmaf(y3, n3, a1);
        }
        for (; j < cnt; j++) {
            int   s  = __shfl_sync(0xffffffffu, rec.x, j);
            float nm = __int_as_float(__shfl_sync(0xffffffffu, rec.y, j));
            const float* hr = h + (size_t)s * FOUT;
            a0 = fmaf(hr[lane], nm, a0);
            if (lane < FOUT - 32) a1 = fmaf(hr[32 + lane], nm, a1);
        }
    }

    if (!LSM) {
        out[(size_t)gw * FOUT + lane] = a0;
        if (lane < FOUT - 32) out[(size_t)gw * FOUT + 32 + lane] = a1;
    } else {
        // fused relu + log_softmax over the 40-feature row held by this warp
        float v0 = fmaxf(a0, 0.f);
        float v1 = (lane < FOUT - 32) ? fmaxf(a1, 0.f) : neg_inf();
        float m = fmaxf(v0, v1);
#pragma unroll
        for (int o = 16; o; o >>= 1) m = fmaxf(m, __shfl_xor_sync(0xffffffffu, m, o));
        float sv = __expf(v0 - m) + ((lane < FOUT - 32) ? __expf(v1 - m) : 0.f);
#pragma unroll
        for (int o = 16; o; o >>= 1) sv += __shfl_xor_sync(0xffffffffu, sv, o);
        float lse = m + __logf(sv);
        out[(size_t)gw * FOUT + lane] = v0 - lse;
        if (lane < FOUT - 32) out[(size_t)gw * FOUT + 32 + lane] = v1 - lse;
    }
}

extern "C" void kernel_launch(void* const* d_in, const int* in_sizes, int n_in,
                              void* d_out, int out_size) {
    const float* x  = (const float*)d_in[0];
    const int*   ei = (const int*)d_in[1];      // int32 [2, NE]
    const float* ew = (const float*)d_in[2];
    const float* W1 = (const float*)d_in[3];
    const float* V1 = (const float*)d_in[4];
    const float* b1 = (const float*)d_in[5];
    const float* W2 = (const float*)d_in[6];
    const float* V2 = (const float*)d_in[7];
    const float* b2 = (const float*)d_in[8];
    float* out = (float*)d_out;

    void *h1p, *acc1p, *h2p, *acc2p;
    cudaGetSymbolAddress(&h1p,   g_h1);
    cudaGetSymbolAddress(&acc1p, g_acc1);
    cudaGetSymbolAddress(&h2p,   g_h2);
    cudaGetSymbolAddress(&acc2p, g_acc2);

    zero_init   <<<(NN + 255) / 256, 256>>>();
    prep_edges  <<<(NE + 255) / 256, 256>>>(ei, ew);
    finish_dinv <<<(NN + 255) / 256, 256>>>();
    scan_phase1 <<<NBLK, SCAN_B>>>();
    scan_phase2 <<<1, 128>>>();
    scan_phase3 <<<(NN + 255) / 256, 256>>>();
    fill_csr    <<<(NE + 255) / 256, 256>>>(ei, ew);

    gemm_dual<64, 48, false><<<(NN + 63) / 64, dim3(48, 4)>>>(
        x, W1, V1, b1, (float*)h1p, (float*)acc1p);

    agg_csr<48, false><<<(NN * 32 + 255) / 256, 256>>>(
        (const float*)h1p, (const float*)acc1p, (float*)acc1p);

    gemm_dual<48, 40, true><<<(NN + 63) / 64, dim3(40, 4)>>>(
        (const float*)acc1p, W2, V2, b2, (float*)h2p, (float*)acc2p);

    agg_csr<40, true><<<(NN * 32 + 255) / 256, 256>>>(
        (const float*)h2p, (const float*)acc2p, out);
}

// round 8
// speedup vs baseline: 1.6342x; 1.0517x over previous
#include <cuda_runtime.h>

#define NN 100000
#define NE 1600000

#define SCAN_B 1024
#define NBLK ((NN + SCAN_B - 1) / SCAN_B)   // 98

// ---- scratch (device globals: no allocation allowed) ----
__device__ float g_deg[NN];
__device__ int   g_cnt[NN];
__device__ int   g_cur[NN];
__device__ int   g_off[NN + 1];
__device__ int   g_bsum[NBLK];
__device__ int   g_bpre[NBLK];
__device__ __align__(16) int2  g_edge[NE];      // CSR slot: {src, norm bits}
__device__ __align__(16) float g_h1[NN * 48];
__device__ __align__(16) float g_acc1[NN * 48];
__device__ __align__(16) float g_h2[NN * 40];
__device__ __align__(16) float g_acc2[NN * 40];

__device__ __forceinline__ float neg_inf() { return __int_as_float(0xff800000); }

__global__ void __launch_bounds__(256) zero_init() {
    int i = blockIdx.x * blockDim.x + threadIdx.x;
    if (i < NN) {
        g_deg[i] = 0.f;
        g_cnt[i] = 0;
        g_cur[i] = 0;
    }
}

__global__ void __launch_bounds__(256)
prep_edges(const int* __restrict__ ei, const float* __restrict__ ew) {
    int e = blockIdx.x * blockDim.x + threadIdx.x;
    if (e >= NE) return;
    int d = ei[NE + e];
    atomicAdd(&g_deg[d], ew[e]);
    atomicAdd(&g_cnt[d], 1);
}

__global__ void __launch_bounds__(256) finish_dinv() {
    int i = blockIdx.x * blockDim.x + threadIdx.x;
    if (i >= NN) return;
    float d = g_deg[i];
    g_deg[i] = (d > 0.f) ? rsqrtf(d) : 0.f;
}

// ---- 3-phase multi-block exclusive scan of g_cnt -> g_off ----
__global__ void __launch_bounds__(SCAN_B) scan_phase1() {
    __shared__ int sums[SCAN_B];
    int tid = threadIdx.x;
    int i = blockIdx.x * SCAN_B + tid;
    int v = (i < NN) ? g_cnt[i] : 0;
    sums[tid] = v;
    __syncthreads();
#pragma unroll
    for (int off = 1; off < SCAN_B; off <<= 1) {
        int t = (tid >= off) ? sums[tid - off] : 0;
        __syncthreads();
        sums[tid] += t;
        __syncthreads();
    }
    if (i < NN) g_off[i] = sums[tid] - v;
    if (tid == SCAN_B - 1) g_bsum[blockIdx.x] = sums[tid];
}

__global__ void __launch_bounds__(128) scan_phase2() {
    __shared__ int sums[128];
    int tid = threadIdx.x;
    int v = (tid < NBLK) ? g_bsum[tid] : 0;
    sums[tid] = v;
    __syncthreads();
#pragma unroll
    for (int off = 1; off < 128; off <<= 1) {
        int t = (tid >= off) ? sums[tid - off] : 0;
        __syncthreads();
        sums[tid] += t;
        __syncthreads();
    }
    if (tid < NBLK) g_bpre[tid] = sums[tid] - v;
}

__global__ void __launch_bounds__(256) scan_phase3() {
    int i = blockIdx.x * blockDim.x + threadIdx.x;
    if (i < NN) g_off[i] += g_bpre[i >> 10];
    if (i == 0) g_off[NN] = NE;
}

__global__ void __launch_bounds__(256)
fill_csr(const int* __restrict__ ei, const float* __restrict__ ew) {
    int e = blockIdx.x * blockDim.x + threadIdx.x;
    if (e >= NE) return;
    int s = ei[e];
    int d = ei[NE + e];
    float nm = g_deg[s] * ew[e] * g_deg[d];
    int pos = g_off[d] + atomicAdd(&g_cur[d], 1);
    g_edge[pos] = make_int2(s, __float_as_int(nm));
}

// Dual GEMM: h = act(x) @ W ; acc = act(x) @ V + b.
template <int FIN, int FOUT, bool RELU>
__global__ void __launch_bounds__(FOUT * 4)
gemm_dual(const float* __restrict__ x, const float* __restrict__ W,
          const float* __restrict__ V, const float* __restrict__ b,
          float* __restrict__ h, float* __restrict__ acc) {
    constexpr int ROWS = 64;
    constexpr int STR  = FIN + 4;
    constexpr int JR   = ROWS / 4;
    __shared__ float2 WV[FIN * FOUT];
    __shared__ float  xs[ROWS * STR];

    const int tid = threadIdx.y * FOUT + threadIdx.x;
    const int nth = FOUT * 4;

    for (int i = tid; i < FIN * FOUT; i += nth)
        WV[i] = make_float2(W[i], V[i]);

    const int row0 = blockIdx.x * ROWS;
    for (int i = tid; i < ROWS * FIN; i += nth) {
        int r = i / FIN, c = i - r * FIN;
        int gr = row0 + r;
        float v = (gr < NN) ? x[(size_t)gr * FIN + c] : 0.f;
        if (RELU) v = fmaxf(v, 0.f);
        xs[r * STR + c] = v;
    }
    __syncthreads();

    const int f = threadIdx.x;
    float aW[JR], aV[JR];
#pragma unroll
    for (int j = 0; j < JR; j++) { aW[j] = 0.f; aV[j] = 0.f; }

    for (int k = 0; k < FIN; k += 4) {
        float2 wv0 = WV[(k + 0) * FOUT + f];
        float2 wv1 = WV[(k + 1) * FOUT + f];
        float2 wv2 = WV[(k + 2) * FOUT + f];
        float2 wv3 = WV[(k + 3) * FOUT + f];
#pragma unroll
        for (int j = 0; j < JR; j++) {
            const float4 xv = *reinterpret_cast<const float4*>(
                &xs[(threadIdx.y + j * 4) * STR + k]);
            aW[j] = fmaf(xv.x, wv0.x, aW[j]); aV[j] = fmaf(xv.x, wv0.y, aV[j]);
            aW[j] = fmaf(xv.y, wv1.x, aW[j]); aV[j] = fmaf(xv.y, wv1.y, aV[j]);
            aW[j] = fmaf(xv.z, wv2.x, aW[j]); aV[j] = fmaf(xv.z, wv2.y, aV[j]);
            aW[j] = fmaf(xv.w, wv3.x, aW[j]); aV[j] = fmaf(xv.w, wv3.y, aV[j]);
        }
    }

    const float bf = b[f];
#pragma unroll
    for (int j = 0; j < JR; j++) {
        int gr = row0 + threadIdx.y + j * 4;
        if (gr < NN) {
            h[(size_t)gr * FOUT + f]   = aW[j];
            acc[(size_t)gr * FOUT + f] = aV[j] + bf;
        }
    }
}

// CSR aggregation: one warp per node. Lanes coalesced-load 32 edge records,
// shuffle-broadcast; float2 gathers (FOUT/2 active lanes), 4 rows in flight.
template <int FOUT, bool LSM>
__global__ void __launch_bounds__(256)
agg_csr(const float* __restrict__ h, const float* __restrict__ accin,
        float* __restrict__ out) {
    constexpr int HL = FOUT / 2;            // 24 or 20 active gather lanes
    int gw = (blockIdx.x * blockDim.x + threadIdx.x) >> 5;
    if (gw >= NN) return;
    int lane = threadIdx.x & 31;
    bool act = lane < HL;

    int e0 = g_off[gw];
    int e1 = g_off[gw + 1];

    float2 a = make_float2(0.f, 0.f);
    if (act) a = reinterpret_cast<const float2*>(accin + (size_t)gw * FOUT)[lane];

    for (int base = e0; base < e1; base += 32) {
        int idx = base + lane;
        int2 rec = (idx < e1) ? g_edge[idx] : make_int2(0, 0);
        int cnt = min(32, e1 - base);
        int j = 0;
        for (; j + 4 <= cnt; j += 4) {
            int s0 = __shfl_sync(0xffffffffu, rec.x, j);
            int s1 = __shfl_sync(0xffffffffu, rec.x, j + 1);
            int s2 = __shfl_sync(0xffffffffu, rec.x, j + 2);
            int s3 = __shfl_sync(0xffffffffu, rec.x, j + 3);
            float n0 = __int_as_float(__shfl_sync(0xffffffffu, rec.y, j));
            float n1 = __int_as_float(__shfl_sync(0xffffffffu, rec.y, j + 1));
            float n2 = __int_as_float(__shfl_sync(0xffffffffu, rec.y, j + 2));
            float n3 = __int_as_float(__shfl_sync(0xffffffffu, rec.y, j + 3));
            float2 v0 = make_float2(0.f, 0.f), v1 = v0, v2 = v0, v3 = v0;
            if (act) {
                v0 = reinterpret_cast<const float2*>(h + (size_t)s0 * FOUT)[lane];
                v1 = reinterpret_cast<const float2*>(h + (size_t)s1 * FOUT)[lane];
                v2 = reinterpret_cast<const float2*>(h + (size_t)s2 * FOUT)[lane];
                v3 = reinterpret_cast<const float2*>(h + (size_t)s3 * FOUT)[lane];
            }
            a.x = fmaf(v0.x, n0, a.x); a.y = fmaf(v0.y, n0, a.y);
            a.x = fmaf(v1.x, n1, a.x); a.y = fmaf(v1.y, n1, a.y);
            a.x = fmaf(v2.x, n2, a.x); a.y = fmaf(v2.y, n2, a.y);
            a.x = fmaf(v3.x, n3, a.x); a.y = fmaf(v3.y, n3, a.y);
        }
        for (; j < cnt; j++) {
            int   s  = __shfl_sync(0xffffffffu, rec.x, j);
            float nm = __int_as_float(__shfl_sync(0xffffffffu, rec.y, j));
            float2 v = make_float2(0.f, 0.f);
            if (act) v = reinterpret_cast<const float2*>(h + (size_t)s * FOUT)[lane];
            a.x = fmaf(v.x, nm, a.x);
            a.y = fmaf(v.y, nm, a.y);
        }
    }

    if (!LSM) {
        if (act) reinterpret_cast<float2*>(out + (size_t)gw * FOUT)[lane] = a;
    } else {
        float vx = act ? fmaxf(a.x, 0.f) : neg_inf();
        float vy = act ? fmaxf(a.y, 0.f) : neg_inf();
        float m = fmaxf(vx, vy);
#pragma unroll
        for (int o = 16; o; o >>= 1) m = fmaxf(m, __shfl_xor_sync(0xffffffffu, m, o));
        float sv = act ? (__expf(vx - m) + __expf(vy - m)) : 0.f;
#pragma unroll
        for (int o = 16; o; o >>= 1) sv += __shfl_xor_sync(0xffffffffu, sv, o);
        float lse = m + __logf(sv);
        if (act)
            reinterpret_cast<float2*>(out + (size_t)gw * FOUT)[lane] =
                make_float2(vx - lse, vy - lse);
    }
}

extern "C" void kernel_launch(void* const* d_in, const int* in_sizes, int n_in,
                              void* d_out, int out_size) {
    const float* x  = (const float*)d_in[0];
    const int*   ei = (const int*)d_in[1];
    const float* ew = (const float*)d_in[2];
    const float* W1 = (const float*)d_in[3];
    const float* V1 = (const float*)d_in[4];
    const float* b1 = (const float*)d_in[5];
    const float* W2 = (const float*)d_in[6];
    const float* V2 = (const float*)d_in[7];
    const float* b2 = (const float*)d_in[8];
    float* out = (float*)d_out;

    void *h1p, *acc1p, *h2p, *acc2p;
    cudaGetSymbolAddress(&h1p,   g_h1);
    cudaGetSymbolAddress(&acc1p, g_acc1);
    cudaGetSymbolAddress(&h2p,   g_h2);
    cudaGetSymbolAddress(&acc2p, g_acc2);

    // Fork a side stream: gemm1 depends only on x/W1/V1 and overlaps the
    // entire edge/CSR pipeline. (Host objects leak: ~2 calls total, no device mem.)
    cudaStream_t s2;
    cudaStreamCreateWithFlags(&s2, cudaStreamNonBlocking);
    cudaEvent_t evF, evJ;
    cudaEventCreateWithFlags(&evF, cudaEventDisableTiming);
    cudaEventCreateWithFlags(&evJ, cudaEventDisableTiming);

    cudaEventRecord(evF, 0);
    cudaStreamWaitEvent(s2, evF, 0);
    gemm_dual<64, 48, false><<<(NN + 63) / 64, dim3(48, 4), 0, s2>>>(
        x, W1, V1, b1, (float*)h1p, (float*)acc1p);
    cudaEventRecord(evJ, s2);

    // Edge/CSR pipeline on the main (capture) stream.
    zero_init   <<<(NN + 255) / 256, 256>>>();
    prep_edges  <<<(NE + 255) / 256, 256>>>(ei, ew);
    finish_dinv <<<(NN + 255) / 256, 256>>>();
    scan_phase1 <<<NBLK, SCAN_B>>>();
    scan_phase2 <<<1, 128>>>();
    scan_phase3 <<<(NN + 255) / 256, 256>>>();
    fill_csr    <<<(NE + 255) / 256, 256>>>(ei, ew);

    cudaStreamWaitEvent(0, evJ, 0);          // join: agg needs gemm1 + CSR

    agg_csr<48, false><<<(NN * 32 + 255) / 256, 256>>>(
        (const float*)h1p, (const float*)acc1p, (float*)acc1p);

    gemm_dual<48, 40, true><<<(NN + 63) / 64, dim3(40, 4)>>>(
        (const float*)acc1p, W2, V2, b2, (float*)h2p, (float*)acc2p);

    agg_csr<40, true><<<(NN * 32 + 255) / 256, 256>>>(
        (const float*)h2p, (const float*)acc2p, out);
}

// round 9
// speedup vs baseline: 1.6459x; 1.0072x over previous
#include <cuda_runtime.h>
#include <cuda_fp16.h>

#define NN 100000
#define NE 1600000

#define SCAN_B 1024
#define NBLK ((NN + SCAN_B - 1) / SCAN_B)   // 98

// ---- scratch (device globals: no allocation allowed) ----
__device__ float g_deg[NN];
__device__ int   g_cnt[NN];
__device__ int   g_cur[NN];
__device__ int   g_off[NN + 1];
__device__ int   g_bsum[NBLK];
__device__ int   g_bpre[NBLK];
__device__ __align__(16) int2   g_edge[NE];     // CSR slot: {src, norm bits}
__device__ __align__(16) __half g_h1[NN * 48];  // fp16 message matrix (layer 1)
__device__ __align__(16) float  g_acc1[NN * 48];
__device__ __align__(16) __half g_h2[NN * 40];  // fp16 message matrix (layer 2)
__device__ __align__(16) float  g_acc2[NN * 40];

__device__ __forceinline__ float neg_inf() { return __int_as_float(0xff800000); }

__global__ void __launch_bounds__(256) zero_init() {
    int i = blockIdx.x * blockDim.x + threadIdx.x;
    if (i < NN) {
        g_deg[i] = 0.f;
        g_cnt[i] = 0;
        g_cur[i] = 0;
    }
}

// Weighted in-degree + count histogram, 4 edges per thread (vector loads).
__global__ void __launch_bounds__(256)
prep_edges(const int* __restrict__ ei, const float* __restrict__ ew) {
    int t = blockIdx.x * blockDim.x + threadIdx.x;
    int e = t * 4;
    if (e + 4 <= NE) {
        int4   d4 = *reinterpret_cast<const int4*>(ei + NE + e);
        float4 w4 = *reinterpret_cast<const float4*>(ew + e);
        atomicAdd(&g_deg[d4.x], w4.x); atomicAdd(&g_cnt[d4.x], 1);
        atomicAdd(&g_deg[d4.y], w4.y); atomicAdd(&g_cnt[d4.y], 1);
        atomicAdd(&g_deg[d4.z], w4.z); atomicAdd(&g_cnt[d4.z], 1);
        atomicAdd(&g_deg[d4.w], w4.w); atomicAdd(&g_cnt[d4.w], 1);
    } else {
        for (int k = e; k < NE; k++) {
            int d = ei[NE + k];
            atomicAdd(&g_deg[d], ew[k]);
            atomicAdd(&g_cnt[d], 1);
        }
    }
}

// Scan phase 1 (+ fused dinv): block-local exclusive scan of g_cnt.
__global__ void __launch_bounds__(SCAN_B) scan_phase1() {
    __shared__ int sums[SCAN_B];
    int tid = threadIdx.x;
    int i = blockIdx.x * SCAN_B + tid;
    int v = (i < NN) ? g_cnt[i] : 0;
    sums[tid] = v;
    if (i < NN) {                       // fused dinv
        float d = g_deg[i];
        g_deg[i] = (d > 0.f) ? rsqrtf(d) : 0.f;
    }
    __syncthreads();
#pragma unroll
    for (int off = 1; off < SCAN_B; off <<= 1) {
        int t = (tid >= off) ? sums[tid - off] : 0;
        __syncthreads();
        sums[tid] += t;
        __syncthreads();
    }
    if (i < NN) g_off[i] = sums[tid] - v;
    if (tid == SCAN_B - 1) g_bsum[blockIdx.x] = sums[tid];
}

__global__ void __launch_bounds__(128) scan_phase2() {
    __shared__ int sums[128];
    int tid = threadIdx.x;
    int v = (tid < NBLK) ? g_bsum[tid] : 0;
    sums[tid] = v;
    __syncthreads();
#pragma unroll
    for (int off = 1; off < 128; off <<= 1) {
        int t = (tid >= off) ? sums[tid - off] : 0;
        __syncthreads();
        sums[tid] += t;
        __syncthreads();
    }
    if (tid < NBLK) g_bpre[tid] = sums[tid] - v;
}

__global__ void __launch_bounds__(256) scan_phase3() {
    int i = blockIdx.x * blockDim.x + threadIdx.x;
    if (i < NN) g_off[i] += g_bpre[i >> 10];
    if (i == 0) g_off[NN] = NE;
}

__global__ void __launch_bounds__(256)
fill_csr(const int* __restrict__ ei, const float* __restrict__ ew) {
    int e = blockIdx.x * blockDim.x + threadIdx.x;
    if (e >= NE) return;
    int s = ei[e];
    int d = ei[NE + e];
    float nm = g_deg[s] * ew[e] * g_deg[d];
    int pos = g_off[d] + atomicAdd(&g_cur[d], 1);
    g_edge[pos] = make_int2(s, __float_as_int(nm));
}

// Dual GEMM: h = act(x) @ W (fp16 out) ; acc = act(x) @ V + b (fp32 out).
template <int FIN, int FOUT, bool RELU>
__global__ void __launch_bounds__(FOUT * 4)
gemm_dual(const float* __restrict__ x, const float* __restrict__ W,
          const float* __restrict__ V, const float* __restrict__ b,
          __half* __restrict__ h, float* __restrict__ acc) {
    constexpr int ROWS = 64;
    constexpr int STR  = FIN + 4;
    constexpr int JR   = ROWS / 4;
    __shared__ float2 WV[FIN * FOUT];
    __shared__ float  xs[ROWS * STR];

    const int tid = threadIdx.y * FOUT + threadIdx.x;
    const int nth = FOUT * 4;

    for (int i = tid; i < FIN * FOUT; i += nth)
        WV[i] = make_float2(W[i], V[i]);

    const int row0 = blockIdx.x * ROWS;
    for (int i = tid; i < ROWS * FIN; i += nth) {
        int r = i / FIN, c = i - r * FIN;
        int gr = row0 + r;
        float v = (gr < NN) ? x[(size_t)gr * FIN + c] : 0.f;
        if (RELU) v = fmaxf(v, 0.f);
        xs[r * STR + c] = v;
    }
    __syncthreads();

    const int f = threadIdx.x;
    float aW[JR], aV[JR];
#pragma unroll
    for (int j = 0; j < JR; j++) { aW[j] = 0.f; aV[j] = 0.f; }

    for (int k = 0; k < FIN; k += 4) {
        float2 wv0 = WV[(k + 0) * FOUT + f];
        float2 wv1 = WV[(k + 1) * FOUT + f];
        float2 wv2 = WV[(k + 2) * FOUT + f];
        float2 wv3 = WV[(k + 3) * FOUT + f];
#pragma unroll
        for (int j = 0; j < JR; j++) {
            const float4 xv = *reinterpret_cast<const float4*>(
                &xs[(threadIdx.y + j * 4) * STR + k]);
            aW[j] = fmaf(xv.x, wv0.x, aW[j]); aV[j] = fmaf(xv.x, wv0.y, aV[j]);
            aW[j] = fmaf(xv.y, wv1.x, aW[j]); aV[j] = fmaf(xv.y, wv1.y, aV[j]);
            aW[j] = fmaf(xv.z, wv2.x, aW[j]); aV[j] = fmaf(xv.z, wv2.y, aV[j]);
            aW[j] = fmaf(xv.w, wv3.x, aW[j]); aV[j] = fmaf(xv.w, wv3.y, aV[j]);
        }
    }

    const float bf = b[f];
#pragma unroll
    for (int j = 0; j < JR; j++) {
        int gr = row0 + threadIdx.y + j * 4;
        if (gr < NN) {
            h[(size_t)gr * FOUT + f]   = __float2half_rn(aW[j]);
            acc[(size_t)gr * FOUT + f] = aV[j] + bf;
        }
    }
}

// CSR aggregation: one warp per node; coalesced edge-record loads +
// shuffle-broadcast; half2 gathers (FOUT/2 active lanes), 4 rows in flight.
template <int FOUT, bool LSM>
__global__ void __launch_bounds__(256)
agg_csr(const __half* __restrict__ h, const float* __restrict__ accin,
        float* __restrict__ out) {
    constexpr int HL = FOUT / 2;            // 24 or 20 active gather lanes
    int gw = (blockIdx.x * blockDim.x + threadIdx.x) >> 5;
    if (gw >= NN) return;
    int lane = threadIdx.x & 31;
    bool act = lane < HL;

    int e0 = g_off[gw];
    int e1 = g_off[gw + 1];

    const __half2* h2p = reinterpret_cast<const __half2*>(h);

    float2 a = make_float2(0.f, 0.f);
    if (act) a = reinterpret_cast<const float2*>(accin + (size_t)gw * FOUT)[lane];

    for (int base = e0; base < e1; base += 32) {
        int idx = base + lane;
        int2 rec = (idx < e1) ? g_edge[idx] : make_int2(0, 0);
        int cnt = min(32, e1 - base);
        int j = 0;
        for (; j + 4 <= cnt; j += 4) {
            int s0 = __shfl_sync(0xffffffffu, rec.x, j);
            int s1 = __shfl_sync(0xffffffffu, rec.x, j + 1);
            int s2 = __shfl_sync(0xffffffffu, rec.x, j + 2);
            int s3 = __shfl_sync(0xffffffffu, rec.x, j + 3);
            float n0 = __int_as_float(__shfl_sync(0xffffffffu, rec.y, j));
            float n1 = __int_as_float(__shfl_sync(0xffffffffu, rec.y, j + 1));
            float n2 = __int_as_float(__shfl_sync(0xffffffffu, rec.y, j + 2));
            float n3 = __int_as_float(__shfl_sync(0xffffffffu, rec.y, j + 3));
            float2 v0 = make_float2(0.f, 0.f), v1 = v0, v2 = v0, v3 = v0;
            if (act) {
                v0 = __half22float2(h2p[(size_t)s0 * HL + lane]);
                v1 = __half22float2(h2p[(size_t)s1 * HL + lane]);
                v2 = __half22float2(h2p[(size_t)s2 * HL + lane]);
                v3 = __half22float2(h2p[(size_t)s3 * HL + lane]);
            }
            a.x = fmaf(v0.x, n0, a.x); a.y = fmaf(v0.y, n0, a.y);
            a.x = fmaf(v1.x, n1, a.x); a.y = fmaf(v1.y, n1, a.y);
            a.x = fmaf(v2.x, n2, a.x); a.y = fmaf(v2.y, n2, a.y);
            a.x = fmaf(v3.x, n3, a.x); a.y = fmaf(v3.y, n3, a.y);
        }
        for (; j < cnt; j++) {
            int   s  = __shfl_sync(0xffffffffu, rec.x, j);
            float nm = __int_as_float(__shfl_sync(0xffffffffu, rec.y, j));
            float2 v = make_float2(0.f, 0.f);
            if (act) v = __half22float2(h2p[(size_t)s * HL + lane]);
            a.x = fmaf(v.x, nm, a.x);
            a.y = fmaf(v.y, nm, a.y);
        }
    }

    if (!LSM) {
        if (act) reinterpret_cast<float2*>(out + (size_t)gw * FOUT)[lane] = a;
    } else {
        float vx = act ? fmaxf(a.x, 0.f) : neg_inf();
        float vy = act ? fmaxf(a.y, 0.f) : neg_inf();
        float m = fmaxf(vx, vy);
#pragma unroll
        for (int o = 16; o; o >>= 1) m = fmaxf(m, __shfl_xor_sync(0xffffffffu, m, o));
        float sv = act ? (__expf(vx - m) + __expf(vy - m)) : 0.f;
#pragma unroll
        for (int o = 16; o; o >>= 1) sv += __shfl_xor_sync(0xffffffffu, sv, o);
        float lse = m + __logf(sv);
        if (act)
            reinterpret_cast<float2*>(out + (size_t)gw * FOUT)[lane] =
                make_float2(vx - lse, vy - lse);
    }
}

extern "C" void kernel_launch(void* const* d_in, const int* in_sizes, int n_in,
                              void* d_out, int out_size) {
    const float* x  = (const float*)d_in[0];
    const int*   ei = (const int*)d_in[1];
    const float* ew = (const float*)d_in[2];
    const float* W1 = (const float*)d_in[3];
    const float* V1 = (const float*)d_in[4];
    const float* b1 = (const float*)d_in[5];
    const float* W2 = (const float*)d_in[6];
    const float* V2 = (const float*)d_in[7];
    const float* b2 = (const float*)d_in[8];
    float* out = (float*)d_out;

    void *h1p, *acc1p, *h2p, *acc2p;
    cudaGetSymbolAddress(&h1p,   g_h1);
    cudaGetSymbolAddress(&acc1p, g_acc1);
    cudaGetSymbolAddress(&h2p,   g_h2);
    cudaGetSymbolAddress(&acc2p, g_acc2);

    cudaStream_t s2;
    cudaStreamCreateWithFlags(&s2, cudaStreamNonBlocking);
    cudaEvent_t evF, evJ;
    cudaEventCreateWithFlags(&evF, cudaEventDisableTiming);
    cudaEventCreateWithFlags(&evJ, cudaEventDisableTiming);

    cudaEventRecord(evF, 0);
    cudaStreamWaitEvent(s2, evF, 0);

    // Launch order matters for observability: ncu profiles launch #4 -> gemm1.
    zero_init   <<<(NN + 255) / 256, 256>>>();                      // 1
    prep_edges  <<<(NE / 4 + 255) / 256, 256>>>(ei, ew);            // 2
    scan_phase1 <<<NBLK, SCAN_B>>>();                               // 3 (+dinv)
    gemm_dual<64, 48, false><<<(NN + 63) / 64, dim3(48, 4), 0, s2>>>(  // 4 (profiled)
        x, W1, V1, b1, (__half*)h1p, (float*)acc1p);
    cudaEventRecord(evJ, s2);
    scan_phase2 <<<1, 128>>>();                                     // 5
    scan_phase3 <<<(NN + 255) / 256, 256>>>();                      // 6
    fill_csr    <<<(NE + 255) / 256, 256>>>(ei, ew);                // 7

    cudaStreamWaitEvent(0, evJ, 0);          // join: agg needs gemm1 + CSR

    agg_csr<48, false><<<(NN * 32 + 255) / 256, 256>>>(             // 8
        (const __half*)h1p, (const float*)acc1p, (float*)acc1p);

    gemm_dual<48, 40, true><<<(NN + 63) / 64, dim3(40, 4)>>>(       // 9
        (const float*)acc1p, W2, V2, b2, (__half*)h2p, (float*)acc2p);

    agg_csr<40, true><<<(NN * 32 + 255) / 256, 256>>>(              // 10
        (const __half*)h2p, (const float*)acc2p, out);
}